// round 11
// baseline (speedup 1.0000x reference)
#include <cuda_runtime.h>
#include <cuda_bf16.h>
#include <cstdint>

// ExpertCapacityBuffer: N tokens, TOP_K=2, 64 experts.
// capacity = ceil(1.25*N*2/64). Flat slot-major: f = slot*N + tok.
// rank(f) = #{g<f : expert(g)==expert(f)}; keep iff rank < capacity.
//
// Key fact: expert e overflows iff total(e) > capacity. If NO expert
// overflows, every element is kept and ranks are irrelevant -> apply is a
// pure streaming copy. Exact rank path kept as a (block-uniform) fallback.
//
// k_count: per-tile rows -> g_cnt (fallback data) + atomic totals -> g_tot.
// k_apply: fast path (no overflow): copy w, idx, mask. slow path: full ranks.

#define NE   64
#define NEP  65              // padded row kills smem bank conflicts
#define TPB  1024
#define EPT  1024
#define MAXROWS 4096

__device__ int g_cnt[MAXROWS][NE];
__device__ int g_tot[NE];    // zero-initialized; reset by last apply block
__device__ int g_done = 0;

// per-warp dtype probe: int64 values <64 => odd 32-bit words of first 256B zero.
__device__ __forceinline__ bool probe_warp(const void* eraw) {
    unsigned x = ((const unsigned*)eraw)[2 * (threadIdx.x & 31) + 1];
    return __ballot_sync(0xFFFFFFFFu, x != 0u) == 0u;
}

// ---------------- Kernel 1: per-tile rows + global totals ----------------
__global__ void __launch_bounds__(TPB)
k_count(const void* __restrict__ eraw, int n_tok, int nbt) {
    __shared__ int hA[32][NEP];
    __shared__ int hB[32][NEP];
    const int t = threadIdx.x, b = blockIdx.x;
    const int warp = t >> 5, lane = t & 31;
    const unsigned lt = (1u << lane) - 1u;

    const int tok = b * EPT + t;
    const bool valid = tok < n_tok;

    int2 v32 = make_int2(0, 0);
    if (valid) v32 = __ldg((const int2*)eraw + tok);      // eager
    const bool is64 = probe_warp(eraw);

    ((int*)hA)[t] = 0; ((int*)hA)[t + TPB] = 0;
    ((int*)hB)[t] = 0; ((int*)hB)[t + TPB] = 0;
    if (t < 32 * NEP - 2 * TPB) { ((int*)hA)[t + 2 * TPB] = 0; ((int*)hB)[t + 2 * TPB] = 0; }
    __syncthreads();

    int e0 = NE + lane, e1 = NE + lane;                    // unique keys if invalid
    if (valid) {
        if (is64) {
            longlong2 v = __ldg((const longlong2*)eraw + tok);
            e0 = (int)v.x & (NE - 1); e1 = (int)v.y & (NE - 1);
        } else {
            e0 = v32.x & (NE - 1); e1 = v32.y & (NE - 1);
        }
    }
    unsigned m0 = __match_any_sync(0xFFFFFFFFu, e0);
    unsigned m1 = __match_any_sync(0xFFFFFFFFu, e1);
    if (valid && !(m0 & lt)) hA[warp][e0] = __popc(m0);
    if (valid && !(m1 & lt)) hB[warp][e1] = __popc(m1);
    __syncthreads();

    // column reduce: warp owns pairs p = warp*4+k (0..127)
    #pragma unroll
    for (int k = 0; k < 4; k++) {
        const int p = warp * 4 + k;
        const int e = p & (NE - 1);
        const bool isB = p >= NE;
        int v = isB ? hB[lane][e] : hA[lane][e];
        #pragma unroll
        for (int d = 16; d > 0; d >>= 1) v += __shfl_xor_sync(0xFFFFFFFFu, v, d);
        if (lane == 0) {
            g_cnt[(isB ? nbt : 0) + b][e] = v;
            if (v) atomicAdd(&g_tot[e], v);
        }
    }
}

// ---------------- Kernel 2: fast copy OR full ranks ----------------
// idx_mode: 0 none, 1 one-word (float), 2 int64
__global__ void __launch_bounds__(TPB)
k_apply(const float* __restrict__ w, const void* __restrict__ eraw,
        int n_tok, int capacity, int nbt,
        float* __restrict__ out_w, void* __restrict__ out_idx, int idx_mode,
        float* __restrict__ out_mask) {
    __shared__ int hA[32][NEP];
    __shared__ int hB[32][NEP];
    __shared__ int partA[16][NE];
    __shared__ int partB[16][NE];
    __shared__ int offA[NE], offB[NE];
    const int t = threadIdx.x, b = blockIdx.x;
    const int warp = t >> 5, lane = t & 31;
    const unsigned lt = (1u << lane) - 1u;

    const int tok = b * EPT + t;
    const bool valid = tok < n_tok;

    // eager data loads
    int2 v32 = make_int2(0, 0);
    float2 wv = make_float2(0.f, 0.f);
    if (valid) {
        v32 = __ldg((const int2*)eraw + tok);
        wv  = __ldg((const float2*)w + tok);
    }
    const bool is64 = probe_warp(eraw);

    // overflow flag (block-uniform, warp-local, no sync)
    const int ta = g_tot[lane], tb = g_tot[lane + 32];
    const bool overflow =
        __ballot_sync(0xFFFFFFFFu, (ta > capacity) || (tb > capacity)) != 0u;

    int e0 = NE + lane, e1 = NE + lane;
    if (valid && (overflow || idx_mode)) {
        if (is64) {
            longlong2 v = __ldg((const longlong2*)eraw + tok);
            e0 = (int)v.x & (NE - 1); e1 = (int)v.y & (NE - 1);
        } else {
            e0 = v32.x & (NE - 1); e1 = v32.y & (NE - 1);
        }
    }

    if (!overflow) {
        // ---------- fast path: everything kept ----------
        if (valid) {
            ((float2*)out_w)[tok] = wv;
            if (idx_mode == 1) {
                ((float2*)out_idx)[tok] = make_float2((float)e0, (float)e1);
            } else if (idx_mode == 2) {
                longlong2 iv; iv.x = e0; iv.y = e1;
                ((longlong2*)out_idx)[tok] = iv;
            }
            if (out_mask) out_mask[tok] = ((wv.x + wv.y) == 0.0f) ? 1.0f : 0.0f;
        }
    } else {
        // ---------- slow path: exact ranks (block-uniform branch) ----------
        // per-block prefix over g_cnt rows (16 chunks x 64 experts)
        {
            const int e = t & (NE - 1), c = t >> 6;
            const int limA = b, limB = nbt + b;
            int accA = 0, accB = 0;
            for (int r = c; r < limB; r += 16) {
                int v = g_cnt[r][e];
                accB += v;
                if (r < limA) accA += v;
            }
            partA[c][e] = accA;
            partB[c][e] = accB;
        }
        ((int*)hA)[t] = 0; ((int*)hA)[t + TPB] = 0;
        ((int*)hB)[t] = 0; ((int*)hB)[t + TPB] = 0;
        if (t < 32 * NEP - 2 * TPB) { ((int*)hA)[t + 2 * TPB] = 0; ((int*)hB)[t + 2 * TPB] = 0; }
        __syncthreads();

        unsigned m0 = __match_any_sync(0xFFFFFFFFu, e0);
        unsigned m1 = __match_any_sync(0xFFFFFFFFu, e1);
        const int wr0 = __popc(m0 & lt), wr1 = __popc(m1 & lt);
        if (valid && wr0 == 0) hA[warp][e0] = __popc(m0);
        if (valid && wr1 == 0) hB[warp][e1] = __popc(m1);
        __syncthreads();

        // shfl exclusive scans over 32 warp-rows + fold chunk partials
        #pragma unroll
        for (int k = 0; k < 4; k++) {
            const int p = warp * 4 + k;
            const int e = p & (NE - 1);
            const bool isB = p >= NE;
            int v = isB ? hB[lane][e] : hA[lane][e];
            int x = v;
            #pragma unroll
            for (int d = 1; d < 32; d <<= 1) {
                int y = __shfl_up_sync(0xFFFFFFFFu, x, d);
                if (lane >= d) x += y;
            }
            if (isB) hB[lane][e] = x - v; else hA[lane][e] = x - v;
            int pv = (lane < 16) ? (isB ? partB[lane][e] : partA[lane][e]) : 0;
            #pragma unroll
            for (int d = 8; d > 0; d >>= 1) pv += __shfl_xor_sync(0xFFFFFFFFu, pv, d);
            if (lane == 0) { if (isB) offB[e] = pv; else offA[e] = pv; }
        }
        __syncthreads();

        if (valid) {
            const int rank0 = offA[e0] + hA[warp][e0] + wr0;
            const int rank1 = offB[e1] + hB[warp][e1] + wr1;
            const float w0 = (rank0 < capacity) ? wv.x : 0.0f;
            const float w1 = (rank1 < capacity) ? wv.y : 0.0f;
            ((float2*)out_w)[tok] = make_float2(w0, w1);
            if (idx_mode == 1) {
                ((float2*)out_idx)[tok] = make_float2((float)e0, (float)e1);
            } else if (idx_mode == 2) {
                longlong2 iv; iv.x = e0; iv.y = e1;
                ((longlong2*)out_idx)[tok] = iv;
            }
            if (out_mask) out_mask[tok] = ((w0 + w1) == 0.0f) ? 1.0f : 0.0f;
        }
    }

    // reset g_tot for next graph replay: last-arriving block (all reads done)
    if (t == 0) {
        if (atomicAdd(&g_done, 1) == (int)gridDim.x - 1) {
            #pragma unroll
            for (int e = 0; e < NE; e++) g_tot[e] = 0;
            g_done = 0;
        }
    }
}

extern "C" void kernel_launch(void* const* d_in, const int* in_sizes, int n_in,
                              void* d_out, int out_size) {
    const float* w    = (const float*)d_in[0];
    const void*  eidx = d_in[1];

    int flat  = in_sizes[0];                 // N * TOP_K
    int n_tok = flat / 2;
    int capacity = (flat * 5 + 255) / 256;   // ceil(1.25 * flat / 64)
    if (capacity < 1) capacity = 1;
    int nbt = (n_tok + EPT - 1) / EPT;
    if (2 * nbt > MAXROWS) nbt = MAXROWS / 2;   // guard (not hit at these sizes)

    float* out = (float*)d_out;
    float* out_w    = out;
    void*  out_idx  = nullptr;
    float* out_mask = nullptr;
    int idx_mode = 0;

    if (out_size >= 3 * flat + n_tok) {          // weights + i64 indices + mask
        idx_mode = 2; out_idx = out + flat; out_mask = out + 3 * flat;
    } else if (out_size >= 2 * flat + n_tok) {   // weights + 1-word indices + mask
        idx_mode = 1; out_idx = out + flat; out_mask = out + 2 * flat;
    } else if (out_size >= flat + n_tok) {       // weights + mask
        out_mask = out + flat;
    }

    k_count<<<nbt, TPB>>>(eidx, n_tok, nbt);
    k_apply<<<nbt, TPB>>>(w, eidx, n_tok, capacity, nbt,
                          out_w, out_idx, idx_mode, out_mask);
}

// round 12
// speedup vs baseline: 1.7619x; 1.7619x over previous
#include <cuda_runtime.h>
#include <cuda_bf16.h>
#include <cstdint>

// ExpertCapacityBuffer: N tokens, TOP_K=2, 64 experts.
// capacity = ceil(1.25*N*2/64). Flat slot-major: f = slot*N + tok.
// rank(f) = #{g<f : expert(g)==expert(f)}; keep iff rank < capacity.
//
// Overflow shortcut: expert e drops anything iff total(e) > capacity.
// If no expert overflows (the common case), apply is a pure streaming copy.
// Exact rank path kept as a block-uniform fallback.

#define NE   64
#define NEP  65              // padded row kills smem bank conflicts
#define TPB  1024
#define EPT  1024
#define MAXROWS 4096

__device__ int g_cnt[MAXROWS][NE];
__device__ int g_tot[NE];    // zero at start; reset by last apply block
__device__ int g_done = 0;

// warp-0 dtype probe: int64 values <64 => odd 32-bit words of first 256B zero.
__device__ __forceinline__ void probe_w0(const void* eraw, int lane, int* s_is64) {
    if (threadIdx.x < 32) {
        unsigned x = ((const unsigned*)eraw)[2 * lane + 1];
        unsigned nz = __ballot_sync(0xFFFFFFFFu, x != 0u);
        if (lane == 0) *s_is64 = (nz == 0u);
    }
}

// per-warp probe (used in apply; measured fine there)
__device__ __forceinline__ bool probe_warp(const void* eraw) {
    unsigned x = ((const unsigned*)eraw)[2 * (threadIdx.x & 31) + 1];
    return __ballot_sync(0xFFFFFFFFu, x != 0u) == 0u;
}

// ---------------- Kernel 1: per-tile rows + global totals (R5 structure) ----------------
__global__ void __launch_bounds__(TPB)
k_count(const void* __restrict__ eraw, int n_tok, int nbt) {
    __shared__ int hA[32][NEP];
    __shared__ int hB[32][NEP];
    __shared__ int s_is64;
    const int t = threadIdx.x, b = blockIdx.x;
    const int warp = t >> 5, lane = t & 31;
    const unsigned lt = (1u << lane) - 1u;

    const int tok = b * EPT + t;
    const bool valid = tok < n_tok;

    // eager int32-interpretation load (in-bounds for either dtype)
    int2 v32 = make_int2(0, 0);
    if (valid) v32 = __ldg((const int2*)eraw + tok);

    ((int*)hA)[t] = 0; ((int*)hA)[t + TPB] = 0;
    ((int*)hB)[t] = 0; ((int*)hB)[t + TPB] = 0;
    if (t < 32 * NEP - 2 * TPB) { ((int*)hA)[t + 2 * TPB] = 0; ((int*)hB)[t + 2 * TPB] = 0; }
    probe_w0(eraw, lane, &s_is64);
    __syncthreads();

    int e0 = NE + lane, e1 = NE + lane;      // unique keys for invalid lanes
    if (valid) {
        if (s_is64) {
            longlong2 v = __ldg((const longlong2*)eraw + tok);
            e0 = (int)v.x & (NE - 1); e1 = (int)v.y & (NE - 1);
        } else {
            e0 = v32.x & (NE - 1); e1 = v32.y & (NE - 1);
        }
    }
    unsigned m0 = __match_any_sync(0xFFFFFFFFu, e0);
    unsigned m1 = __match_any_sync(0xFFFFFFFFu, e1);
    if (valid && !(m0 & lt)) hA[warp][e0] = __popc(m0);
    if (valid && !(m1 & lt)) hB[warp][e1] = __popc(m1);
    __syncthreads();

    // serial column reduce by threads 0-127 (R5-proven), + one atomic each
    if (t < NE) {
        int s = 0;
        #pragma unroll
        for (int w = 0; w < 32; w++) s += hA[w][t];
        g_cnt[b][t] = s;
        if (s) atomicAdd(&g_tot[t], s);
    } else if (t < 2 * NE) {
        const int e = t - NE;
        int s = 0;
        #pragma unroll
        for (int w = 0; w < 32; w++) s += hB[w][e];
        g_cnt[nbt + b][e] = s;
        if (s) atomicAdd(&g_tot[e], s);
    }
}

// ---------------- Kernel 2: fast copy OR full ranks (R11-proven) ----------------
// idx_mode: 0 none, 1 one-word (float), 2 int64
__global__ void __launch_bounds__(TPB)
k_apply(const float* __restrict__ w, const void* __restrict__ eraw,
        int n_tok, int capacity, int nbt,
        float* __restrict__ out_w, void* __restrict__ out_idx, int idx_mode,
        float* __restrict__ out_mask) {
    __shared__ int hA[32][NEP];
    __shared__ int hB[32][NEP];
    __shared__ int partA[16][NE];
    __shared__ int partB[16][NE];
    __shared__ int offA[NE], offB[NE];
    const int t = threadIdx.x, b = blockIdx.x;
    const int warp = t >> 5, lane = t & 31;
    const unsigned lt = (1u << lane) - 1u;

    const int tok = b * EPT + t;
    const bool valid = tok < n_tok;

    // eager data loads
    int2 v32 = make_int2(0, 0);
    float2 wv = make_float2(0.f, 0.f);
    if (valid) {
        v32 = __ldg((const int2*)eraw + tok);
        wv  = __ldg((const float2*)w + tok);
    }
    const bool is64 = probe_warp(eraw);

    // overflow flag (block-uniform, warp-local, no sync)
    const int ta = g_tot[lane], tb = g_tot[lane + 32];
    const bool overflow =
        __ballot_sync(0xFFFFFFFFu, (ta > capacity) || (tb > capacity)) != 0u;

    int e0 = NE + lane, e1 = NE + lane;
    if (valid && (overflow || idx_mode)) {
        if (is64) {
            longlong2 v = __ldg((const longlong2*)eraw + tok);
            e0 = (int)v.x & (NE - 1); e1 = (int)v.y & (NE - 1);
        } else {
            e0 = v32.x & (NE - 1); e1 = v32.y & (NE - 1);
        }
    }

    if (!overflow) {
        // ---------- fast path: everything kept ----------
        if (valid) {
            ((float2*)out_w)[tok] = wv;
            if (idx_mode == 1) {
                ((float2*)out_idx)[tok] = make_float2((float)e0, (float)e1);
            } else if (idx_mode == 2) {
                longlong2 iv; iv.x = e0; iv.y = e1;
                ((longlong2*)out_idx)[tok] = iv;
            }
            if (out_mask) out_mask[tok] = ((wv.x + wv.y) == 0.0f) ? 1.0f : 0.0f;
        }
    } else {
        // ---------- slow path: exact ranks (block-uniform branch) ----------
        {
            const int e = t & (NE - 1), c = t >> 6;
            const int limA = b, limB = nbt + b;
            int accA = 0, accB = 0;
            for (int r = c; r < limB; r += 16) {
                int v = g_cnt[r][e];
                accB += v;
                if (r < limA) accA += v;
            }
            partA[c][e] = accA;
            partB[c][e] = accB;
        }
        ((int*)hA)[t] = 0; ((int*)hA)[t + TPB] = 0;
        ((int*)hB)[t] = 0; ((int*)hB)[t + TPB] = 0;
        if (t < 32 * NEP - 2 * TPB) { ((int*)hA)[t + 2 * TPB] = 0; ((int*)hB)[t + 2 * TPB] = 0; }
        __syncthreads();

        unsigned m0 = __match_any_sync(0xFFFFFFFFu, e0);
        unsigned m1 = __match_any_sync(0xFFFFFFFFu, e1);
        const int wr0 = __popc(m0 & lt), wr1 = __popc(m1 & lt);
        if (valid && wr0 == 0) hA[warp][e0] = __popc(m0);
        if (valid && wr1 == 0) hB[warp][e1] = __popc(m1);
        __syncthreads();

        #pragma unroll
        for (int k = 0; k < 4; k++) {
            const int p = warp * 4 + k;
            const int e = p & (NE - 1);
            const bool isB = p >= NE;
            int v = isB ? hB[lane][e] : hA[lane][e];
            int x = v;
            #pragma unroll
            for (int d = 1; d < 32; d <<= 1) {
                int y = __shfl_up_sync(0xFFFFFFFFu, x, d);
                if (lane >= d) x += y;
            }
            if (isB) hB[lane][e] = x - v; else hA[lane][e] = x - v;
            int pv = (lane < 16) ? (isB ? partB[lane][e] : partA[lane][e]) : 0;
            #pragma unroll
            for (int d = 8; d > 0; d >>= 1) pv += __shfl_xor_sync(0xFFFFFFFFu, pv, d);
            if (lane == 0) { if (isB) offB[e] = pv; else offA[e] = pv; }
        }
        __syncthreads();

        if (valid) {
            const int rank0 = offA[e0] + hA[warp][e0] + wr0;
            const int rank1 = offB[e1] + hB[warp][e1] + wr1;
            const float w0 = (rank0 < capacity) ? wv.x : 0.0f;
            const float w1 = (rank1 < capacity) ? wv.y : 0.0f;
            ((float2*)out_w)[tok] = make_float2(w0, w1);
            if (idx_mode == 1) {
                ((float2*)out_idx)[tok] = make_float2((float)e0, (float)e1);
            } else if (idx_mode == 2) {
                longlong2 iv; iv.x = e0; iv.y = e1;
                ((longlong2*)out_idx)[tok] = iv;
            }
            if (out_mask) out_mask[tok] = ((w0 + w1) == 0.0f) ? 1.0f : 0.0f;
        }
    }

    // reset g_tot for next graph replay (last-arriving block; all reads done)
    if (t == 0) {
        if (atomicAdd(&g_done, 1) == (int)gridDim.x - 1) {
            #pragma unroll
            for (int e = 0; e < NE; e++) g_tot[e] = 0;
            g_done = 0;
        }
    }
}

extern "C" void kernel_launch(void* const* d_in, const int* in_sizes, int n_in,
                              void* d_out, int out_size) {
    const float* w    = (const float*)d_in[0];
    const void*  eidx = d_in[1];

    int flat  = in_sizes[0];                 // N * TOP_K
    int n_tok = flat / 2;
    int capacity = (flat * 5 + 255) / 256;   // ceil(1.25 * flat / 64)
    if (capacity < 1) capacity = 1;
    int nbt = (n_tok + EPT - 1) / EPT;
    if (2 * nbt > MAXROWS) nbt = MAXROWS / 2;   // guard (not hit at these sizes)

    float* out = (float*)d_out;
    float* out_w    = out;
    void*  out_idx  = nullptr;
    float* out_mask = nullptr;
    int idx_mode = 0;

    if (out_size >= 3 * flat + n_tok) {          // weights + i64 indices + mask
        idx_mode = 2; out_idx = out + flat; out_mask = out + 3 * flat;
    } else if (out_size >= 2 * flat + n_tok) {   // weights + 1-word indices + mask
        idx_mode = 1; out_idx = out + flat; out_mask = out + 2 * flat;
    } else if (out_size >= flat + n_tok) {       // weights + mask
        out_mask = out + flat;
    }

    k_count<<<nbt, TPB>>>(eidx, n_tok, nbt);
    k_apply<<<nbt, TPB>>>(w, eidx, n_tok, capacity, nbt,
                          out_w, out_idx, idx_mode, out_mask);
}